// round 1
// baseline (speedup 1.0000x reference)
#include <cuda_runtime.h>
#include <cuda_bf16.h>
#include <math.h>

#define NN 100000
#define NE 1600000
#define INF 128
#define HID 32
#define NPAIRS 4096

// scratch (device globals — no allocation in kernel_launch)
__device__ float g_xb[NN * 64];        // per-node basis outputs [N][2*32]
__device__ float g_agg[NN * 32];       // aggregation buffer (init = loop term + bias)
__device__ float g_h1[NN * 32];
__device__ float g_h2[NN * 32];
__device__ float g_h3[NN * 32];

// ---------------------------------------------------------------------------
// Transform: out96[n][j] = sum_d x[n][d] * Wall[d][j]
//   j in [0,64): xb basis outputs (b = j/32, o = j%32)  -> g_xb
//   j in [64,96): self-loop output + bias               -> g_agg (pre-init for edge atomics)
// blockDim = 96, 32 nodes per block.
// ---------------------------------------------------------------------------
template <int DIN>
__global__ void transform_kernel(const float* __restrict__ xin,
                                 const float* __restrict__ V,       // [2][DIN][32]
                                 const float* __restrict__ loopw,   // [DIN][32]
                                 const float* __restrict__ bias,    // [32]
                                 float* __restrict__ xb,            // [NN][64]
                                 float* __restrict__ agg,           // [NN][32]
                                 int nnodes)
{
    extern __shared__ float sm[];
    float* Ws = sm;                 // DIN*96
    float* xs = sm + DIN * 96;      // 32*DIN
    const int tid = threadIdx.x;    // 0..95

    // Load weights: thread tid owns column j = tid for all d (coalesced over j).
    for (int idx = tid; idx < DIN * 96; idx += 96) {
        int d = idx / 96;
        int j = idx % 96;
        float w;
        if (j < 64) w = V[(j >> 5) * DIN * 32 + d * 32 + (j & 31)];
        else        w = loopw[d * 32 + (j - 64)];
        Ws[idx] = w;
    }
    const int base = blockIdx.x * 32;
    for (int idx = tid; idx < 32 * DIN; idx += 96) {
        int n = idx / DIN;
        int node = base + n;
        xs[idx] = (node < nnodes) ? xin[(long)node * DIN + (idx % DIN)] : 0.f;
    }
    __syncthreads();

    const float binit = (tid >= 64) ? bias[tid - 64] : 0.f;

#pragma unroll 1
    for (int n0 = 0; n0 < 32; n0 += 4) {
        float a0 = binit, a1 = binit, a2 = binit, a3 = binit;
        const float* x0 = xs + (n0 + 0) * DIN;
        const float* x1 = xs + (n0 + 1) * DIN;
        const float* x2 = xs + (n0 + 2) * DIN;
        const float* x3 = xs + (n0 + 3) * DIN;
#pragma unroll 8
        for (int d = 0; d < DIN; d++) {
            float w = Ws[d * 96 + tid];
            a0 = fmaf(x0[d], w, a0);
            a1 = fmaf(x1[d], w, a1);
            a2 = fmaf(x2[d], w, a2);
            a3 = fmaf(x3[d], w, a3);
        }
        int n = base + n0;
        if (tid < 64) {
            if (n + 0 < nnodes) xb[(long)(n + 0) * 64 + tid] = a0;
            if (n + 1 < nnodes) xb[(long)(n + 1) * 64 + tid] = a1;
            if (n + 2 < nnodes) xb[(long)(n + 2) * 64 + tid] = a2;
            if (n + 3 < nnodes) xb[(long)(n + 3) * 64 + tid] = a3;
        } else {
            int o = tid - 64;
            if (n + 0 < nnodes) agg[(long)(n + 0) * 32 + o] = a0;
            if (n + 1 < nnodes) agg[(long)(n + 1) * 32 + o] = a1;
            if (n + 2 < nnodes) agg[(long)(n + 2) * 32 + o] = a2;
            if (n + 3 < nnodes) agg[(long)(n + 3) * 32 + o] = a3;
        }
    }
}

// ---------------------------------------------------------------------------
// Edge kernel: one warp per edge.
// msg[o] = mask*(comp[r][0]*xb[s][o] + comp[r][1]*xb[s][32+o]); atomicAdd agg[d][o].
// ---------------------------------------------------------------------------
__global__ void edge_kernel(const float* __restrict__ xb,
                            float* __restrict__ agg,
                            const int* __restrict__ etype,
                            const int* __restrict__ src,
                            const int* __restrict__ dst,
                            const float* __restrict__ mask,
                            const float* __restrict__ comp,  // [5][2]
                            int nedges)
{
    const int lane = threadIdx.x & 31;
    const int e = blockIdx.x * (blockDim.x >> 5) + (threadIdx.x >> 5);
    if (e >= nedges) return;
    const int r = __ldg(&etype[e]);
    const float m = __ldg(&mask[e]);
    const int s = __ldg(&src[e]);
    const int d = __ldg(&dst[e]);
    const float c0 = __ldg(&comp[r * 2 + 0]) * m;
    const float c1 = __ldg(&comp[r * 2 + 1]) * m;
    const float* xrow = xb + (long)s * 64;
    const float v = c0 * __ldg(&xrow[lane]) + c1 * __ldg(&xrow[32 + lane]);
    atomicAdd(&agg[(long)d * 32 + lane], v);
}

// ---------------------------------------------------------------------------
// Finalize: h = tanh(agg), vectorized float4.
// ---------------------------------------------------------------------------
__global__ void tanh_kernel(const float4* __restrict__ agg, float4* __restrict__ h, int n4)
{
    int i = blockIdx.x * blockDim.x + threadIdx.x;
    if (i >= n4) return;
    float4 a = agg[i];
    float4 o;
    o.x = tanhf(a.x); o.y = tanhf(a.y); o.z = tanhf(a.z); o.w = tanhf(a.w);
    h[i] = o;
}

// ---------------------------------------------------------------------------
// Head: out[p] = relu(feats[p]@w1 + bw1) @ w2 + bw2
// feats[p] = [h1[u],h2[u],h3[u],h1[i],h2[i],h3[i]]  (192)
// 128 threads (one per hidden unit), w1 staged in smem, 32 pairs/block.
// ---------------------------------------------------------------------------
#define PPB 32
__global__ void head_kernel(const float* __restrict__ h1,
                            const float* __restrict__ h2,
                            const float* __restrict__ h3,
                            const int* __restrict__ users,
                            const int* __restrict__ items,
                            const float* __restrict__ w1,   // [192][128]
                            const float* __restrict__ bw1,  // [128]
                            const float* __restrict__ w2,   // [128]
                            const float* __restrict__ bw2,  // [1]
                            float* __restrict__ out,
                            int npairs)
{
    extern __shared__ float sm[];
    float* w1s = sm;              // 192*128
    float* feats = sm + 24576;    // 192
    const int tid = threadIdx.x;  // 0..127

    for (int idx = tid; idx < 24576; idx += 128) w1s[idx] = w1[idx];
    const float bb = bw1[tid];
    const float wv2 = w2[tid];
    const float b2v = bw2[0];
    __shared__ float red[4];
    __syncthreads();

    const int pend = min((blockIdx.x + 1) * PPB, npairs);
    for (int p = blockIdx.x * PPB; p < pend; p++) {
        if (tid < 96) {
            int u = __ldg(&users[p]);
            int it = __ldg(&items[p]);
            int o = tid & 31;
            const float* hu = (tid < 32) ? h1 : (tid < 64) ? h2 : h3;
            feats[tid] = hu[(long)u * 32 + o];
            feats[96 + tid] = hu[(long)it * 32 + o];
        }
        __syncthreads();
        float acc = bb;
#pragma unroll 16
        for (int k = 0; k < 192; k++)
            acc = fmaf(feats[k], w1s[k * 128 + tid], acc);
        float hv = fmaxf(acc, 0.f) * wv2;
#pragma unroll
        for (int off = 16; off; off >>= 1) hv += __shfl_down_sync(0xFFFFFFFFu, hv, off);
        if ((tid & 31) == 0) red[tid >> 5] = hv;
        __syncthreads();
        if (tid == 0) out[p] = red[0] + red[1] + red[2] + red[3] + b2v;
        __syncthreads();
    }
}

// ---------------------------------------------------------------------------
extern "C" void kernel_launch(void* const* d_in, const int* in_sizes, int n_in,
                              void* d_out, int out_size)
{
    const float* x        = (const float*)d_in[0];
    const float* emask    = (const float*)d_in[1];
    const int*   etype    = (const int*)d_in[2];
    const int*   src      = (const int*)d_in[3];
    const int*   dst      = (const int*)d_in[4];
    const int*   users    = (const int*)d_in[5];
    const int*   items    = (const int*)d_in[6];
    const float* V1       = (const float*)d_in[7];
    const float* comp1    = (const float*)d_in[8];
    const float* loop1    = (const float*)d_in[9];
    const float* b1       = (const float*)d_in[10];
    const float* V2       = (const float*)d_in[11];
    const float* comp2    = (const float*)d_in[12];
    const float* loop2    = (const float*)d_in[13];
    const float* b2       = (const float*)d_in[14];
    const float* V3       = (const float*)d_in[15];
    const float* comp3    = (const float*)d_in[16];
    const float* loop3    = (const float*)d_in[17];
    const float* b3       = (const float*)d_in[18];
    const float* w1       = (const float*)d_in[19];
    const float* bw1      = (const float*)d_in[20];
    const float* w2       = (const float*)d_in[21];
    const float* bw2      = (const float*)d_in[22];
    float* out = (float*)d_out;

    float *xb, *agg, *h1, *h2, *h3;
    cudaGetSymbolAddress((void**)&xb,  g_xb);
    cudaGetSymbolAddress((void**)&agg, g_agg);
    cudaGetSymbolAddress((void**)&h1,  g_h1);
    cudaGetSymbolAddress((void**)&h2,  g_h2);
    cudaGetSymbolAddress((void**)&h3,  g_h3);

    // smem sizes
    const int smem_t1 = (INF * 96 + 32 * INF) * 4;   // 64 KB
    const int smem_t2 = (HID * 96 + 32 * HID) * 4;   // 16 KB
    const int smem_hd = (24576 + 192) * 4;           // ~99 KB
    static bool attr_set = false;
    cudaFuncSetAttribute(transform_kernel<INF>, cudaFuncAttributeMaxDynamicSharedMemorySize, smem_t1);
    cudaFuncSetAttribute(transform_kernel<HID>, cudaFuncAttributeMaxDynamicSharedMemorySize, smem_t2);
    cudaFuncSetAttribute(head_kernel, cudaFuncAttributeMaxDynamicSharedMemorySize, smem_hd);
    (void)attr_set;

    const int tgrid = (NN + 31) / 32;                 // 3125
    const int egrid = (NE + 7) / 8;                   // 200000 (8 warps/block)
    const int n4 = NN * 32 / 4;
    const int fgrid = (n4 + 255) / 256;

    // Layer 1
    transform_kernel<INF><<<tgrid, 96, smem_t1>>>(x, V1, loop1, b1, xb, agg, NN);
    edge_kernel<<<egrid, 256>>>(xb, agg, etype, src, dst, emask, comp1, NE);
    tanh_kernel<<<fgrid, 256>>>((const float4*)agg, (float4*)h1, n4);
    // Layer 2
    transform_kernel<HID><<<tgrid, 96, smem_t2>>>(h1, V2, loop2, b2, xb, agg, NN);
    edge_kernel<<<egrid, 256>>>(xb, agg, etype, src, dst, emask, comp2, NE);
    tanh_kernel<<<fgrid, 256>>>((const float4*)agg, (float4*)h2, n4);
    // Layer 3
    transform_kernel<HID><<<tgrid, 96, smem_t2>>>(h2, V3, loop3, b3, xb, agg, NN);
    edge_kernel<<<egrid, 256>>>(xb, agg, etype, src, dst, emask, comp3, NE);
    tanh_kernel<<<fgrid, 256>>>((const float4*)agg, (float4*)h3, n4);
    // Head
    head_kernel<<<(NPAIRS + PPB - 1) / PPB, 128, smem_hd>>>(
        h1, h2, h3, users, items, w1, bw1, w2, bw2, out, NPAIRS);
}

// round 2
// speedup vs baseline: 1.4960x; 1.4960x over previous
#include <cuda_runtime.h>
#include <cuda_bf16.h>
#include <math.h>

#define NN 100000
#define NE 1600000
#define INF 128
#define HID 32
#define NPAIRS 4096
#define SCAN_BS 1024
#define NB ((NN + SCAN_BS - 1) / SCAN_BS)   // 98

// scratch (device globals — no allocations anywhere)
__device__ float g_xb[NN * 64];        // per-node basis outputs, interleaved [n][o][b]
__device__ float g_agg[NN * 32];       // aggregation init (loop term + bias)
__device__ float g_h1[NN * 32];
__device__ float g_h2[NN * 32];
__device__ float g_h3[NN * 32];
// CSR scratch
__device__ int   g_deg[NN];
__device__ int   g_bsum[NB + 1];
__device__ int   g_rowptr[NN + 1];
__device__ int   g_cursor[NN];
__device__ int4  g_meta[NE];           // {src, etype, mask_bits, pad} sorted by dst

// ---------------------------------------------------------------------------
// Transform: out96[n][j] = sum_d x[n][d] * Wall[d][j]
//   j in [0,64): basis outputs -> g_xb interleaved at n*64 + o*2 + b
//   j in [64,96): self-loop + bias -> g_agg
// ---------------------------------------------------------------------------
template <int DIN>
__global__ void transform_kernel(const float* __restrict__ xin,
                                 const float* __restrict__ V,       // [2][DIN][32]
                                 const float* __restrict__ loopw,   // [DIN][32]
                                 const float* __restrict__ bias,    // [32]
                                 float* __restrict__ xb,
                                 float* __restrict__ agg,
                                 int nnodes)
{
    extern __shared__ float sm[];
    float* Ws = sm;                 // DIN*96
    float* xs = sm + DIN * 96;      // 32*DIN
    const int tid = threadIdx.x;    // 0..95

    for (int idx = tid; idx < DIN * 96; idx += 96) {
        int d = idx / 96;
        int j = idx % 96;
        float w;
        if (j < 64) w = V[(j >> 5) * DIN * 32 + d * 32 + (j & 31)];
        else        w = loopw[d * 32 + (j - 64)];
        Ws[idx] = w;
    }
    const int base = blockIdx.x * 32;
    for (int idx = tid; idx < 32 * DIN; idx += 96) {
        int n = idx / DIN;
        int node = base + n;
        xs[idx] = (node < nnodes) ? xin[(long)node * DIN + (idx % DIN)] : 0.f;
    }
    __syncthreads();

    const float binit = (tid >= 64) ? bias[tid - 64] : 0.f;
    // interleaved xb index for this thread's (b,o)
    const int xbi = (tid < 64) ? ((tid & 31) * 2 + (tid >> 5)) : 0;

#pragma unroll 1
    for (int n0 = 0; n0 < 32; n0 += 4) {
        float a0 = binit, a1 = binit, a2 = binit, a3 = binit;
        const float* x0 = xs + (n0 + 0) * DIN;
        const float* x1 = xs + (n0 + 1) * DIN;
        const float* x2 = xs + (n0 + 2) * DIN;
        const float* x3 = xs + (n0 + 3) * DIN;
#pragma unroll 4
        for (int d = 0; d < DIN; d += 4) {
            float w0 = Ws[(d + 0) * 96 + tid];
            float w1 = Ws[(d + 1) * 96 + tid];
            float w2 = Ws[(d + 2) * 96 + tid];
            float w3 = Ws[(d + 3) * 96 + tid];
            float4 v0 = *(const float4*)(x0 + d);
            float4 v1 = *(const float4*)(x1 + d);
            float4 v2 = *(const float4*)(x2 + d);
            float4 v3 = *(const float4*)(x3 + d);
            a0 = fmaf(v0.x, w0, fmaf(v0.y, w1, fmaf(v0.z, w2, fmaf(v0.w, w3, a0))));
            a1 = fmaf(v1.x, w0, fmaf(v1.y, w1, fmaf(v1.z, w2, fmaf(v1.w, w3, a1))));
            a2 = fmaf(v2.x, w0, fmaf(v2.y, w1, fmaf(v2.z, w2, fmaf(v2.w, w3, a2))));
            a3 = fmaf(v3.x, w0, fmaf(v3.y, w1, fmaf(v3.z, w2, fmaf(v3.w, w3, a3))));
        }
        int n = base + n0;
        if (tid < 64) {
            if (n + 0 < nnodes) xb[(long)(n + 0) * 64 + xbi] = a0;
            if (n + 1 < nnodes) xb[(long)(n + 1) * 64 + xbi] = a1;
            if (n + 2 < nnodes) xb[(long)(n + 2) * 64 + xbi] = a2;
            if (n + 3 < nnodes) xb[(long)(n + 3) * 64 + xbi] = a3;
        } else {
            int o = tid - 64;
            if (n + 0 < nnodes) agg[(long)(n + 0) * 32 + o] = a0;
            if (n + 1 < nnodes) agg[(long)(n + 1) * 32 + o] = a1;
            if (n + 2 < nnodes) agg[(long)(n + 2) * 32 + o] = a2;
            if (n + 3 < nnodes) agg[(long)(n + 3) * 32 + o] = a3;
        }
    }
}

// ------------------------ CSR build ---------------------------------------
__global__ void k_zero(int* p, int n)
{
    int i = blockIdx.x * blockDim.x + threadIdx.x;
    if (i < n) p[i] = 0;
}

__global__ void k_hist(const int* __restrict__ dst, int* __restrict__ deg, int ne)
{
    int i = blockIdx.x * blockDim.x + threadIdx.x;
    if (i < ne) atomicAdd(&deg[dst[i]], 1);
}

__global__ void k_blocksum(const int* __restrict__ deg, int* __restrict__ bsum, int n)
{
    __shared__ int wsum[32];
    int i = blockIdx.x * SCAN_BS + threadIdx.x;
    int v = (i < n) ? deg[i] : 0;
#pragma unroll
    for (int o = 16; o; o >>= 1) v += __shfl_down_sync(0xFFFFFFFFu, v, o);
    int lane = threadIdx.x & 31, wid = threadIdx.x >> 5;
    if (lane == 0) wsum[wid] = v;
    __syncthreads();
    if (wid == 0) {
        int x = wsum[lane];
#pragma unroll
        for (int o = 16; o; o >>= 1) x += __shfl_down_sync(0xFFFFFFFFu, x, o);
        if (lane == 0) bsum[blockIdx.x] = x;
    }
}

__global__ void k_scantop(int* __restrict__ bsum, int nb, int* __restrict__ rowptr_end)
{
    // single block, 128 threads; nb <= 128
    __shared__ int s[128];
    int t = threadIdx.x;
    int v = (t < nb) ? bsum[t] : 0;
    s[t] = v;
    __syncthreads();
#pragma unroll
    for (int o = 1; o < 128; o <<= 1) {
        int y = (t >= o) ? s[t - o] : 0;
        __syncthreads();
        s[t] += y;
        __syncthreads();
    }
    if (t < nb) bsum[t] = s[t] - v;   // exclusive
    if (t == 127) *rowptr_end = s[127];
}

__global__ void k_scanapply(const int* __restrict__ deg, const int* __restrict__ bsum,
                            int* __restrict__ rowptr, int* __restrict__ cursor, int n)
{
    __shared__ int wsum[32];
    int i = blockIdx.x * SCAN_BS + threadIdx.x;
    int v = (i < n) ? deg[i] : 0;
    int lane = threadIdx.x & 31, wid = threadIdx.x >> 5;
    unsigned fm = 0xFFFFFFFFu;
    int x = v;
#pragma unroll
    for (int o = 1; o < 32; o <<= 1) {
        int y = __shfl_up_sync(fm, x, o);
        if (lane >= o) x += y;
    }
    if (lane == 31) wsum[wid] = x;
    __syncthreads();
    if (wid == 0) {
        int w = wsum[lane];
        int wx = w;
#pragma unroll
        for (int o = 1; o < 32; o <<= 1) {
            int y = __shfl_up_sync(fm, wx, o);
            if (lane >= o) wx += y;
        }
        wsum[lane] = wx - w;   // exclusive warp offsets
    }
    __syncthreads();
    int excl = (x - v) + wsum[wid] + bsum[blockIdx.x];
    if (i < n) { rowptr[i] = excl; cursor[i] = excl; }
}

__global__ void k_scatter(const int* __restrict__ src, const int* __restrict__ dst,
                          const int* __restrict__ etype, const float* __restrict__ mask,
                          int* __restrict__ cursor, int4* __restrict__ meta, int ne)
{
    int e = blockIdx.x * blockDim.x + threadIdx.x;
    if (e >= ne) return;
    int d = dst[e];
    int pos = atomicAdd(&cursor[d], 1);
    meta[pos] = make_int4(src[e], etype[e], __float_as_int(mask[e]), 0);
}

// ---------------------------------------------------------------------------
// Aggregate: warp per node. acc = agginit; for each in-edge:
//   acc += m*(c0*xb[s][o][0] + c1*xb[s][o][1]);  h = tanh(acc)
// ---------------------------------------------------------------------------
__global__ void k_aggregate(const float* __restrict__ xb,
                            const float* __restrict__ agginit,
                            const int* __restrict__ rowptr,
                            const int4* __restrict__ meta,
                            const float* __restrict__ comp,  // [5][2]
                            float* __restrict__ h, int nn)
{
    __shared__ float cl[16];
    if (threadIdx.x < 10) cl[threadIdx.x] = comp[threadIdx.x];
    __syncthreads();
    const int lane = threadIdx.x & 31;
    const int w = (blockIdx.x * blockDim.x + threadIdx.x) >> 5;
    if (w >= nn) return;
    float acc = agginit[(long)w * 32 + lane];
    const int end = rowptr[w + 1];
#pragma unroll 2
    for (int i = rowptr[w]; i < end; i++) {
        int4 md = __ldg(&meta[i]);
        float2 v = *(const float2*)(xb + (long)md.x * 64 + lane * 2);
        float c0 = cl[md.y * 2], c1 = cl[md.y * 2 + 1];
        acc = fmaf(__int_as_float(md.z), fmaf(c0, v.x, c1 * v.y), acc);
    }
    h[(long)w * 32 + lane] = tanhf(acc);
}

// ---------------------------------------------------------------------------
// Head (unchanged from R1)
// ---------------------------------------------------------------------------
#define PPB 32
__global__ void head_kernel(const float* __restrict__ h1,
                            const float* __restrict__ h2,
                            const float* __restrict__ h3,
                            const int* __restrict__ users,
                            const int* __restrict__ items,
                            const float* __restrict__ w1,   // [192][128]
                            const float* __restrict__ bw1,
                            const float* __restrict__ w2,
                            const float* __restrict__ bw2,
                            float* __restrict__ out,
                            int npairs)
{
    extern __shared__ float sm[];
    float* w1s = sm;
    float* feats = sm + 24576;
    const int tid = threadIdx.x;

    for (int idx = tid; idx < 24576; idx += 128) w1s[idx] = w1[idx];
    const float bb = bw1[tid];
    const float wv2 = w2[tid];
    const float b2v = bw2[0];
    __shared__ float red[4];
    __syncthreads();

    const int pend = min((blockIdx.x + 1) * PPB, npairs);
    for (int p = blockIdx.x * PPB; p < pend; p++) {
        if (tid < 96) {
            int u = __ldg(&users[p]);
            int it = __ldg(&items[p]);
            int o = tid & 31;
            const float* hu = (tid < 32) ? h1 : (tid < 64) ? h2 : h3;
            feats[tid] = hu[(long)u * 32 + o];
            feats[96 + tid] = hu[(long)it * 32 + o];
        }
        __syncthreads();
        float acc = bb;
#pragma unroll 16
        for (int k = 0; k < 192; k++)
            acc = fmaf(feats[k], w1s[k * 128 + tid], acc);
        float hv = fmaxf(acc, 0.f) * wv2;
#pragma unroll
        for (int off = 16; off; off >>= 1) hv += __shfl_down_sync(0xFFFFFFFFu, hv, off);
        if ((tid & 31) == 0) red[tid >> 5] = hv;
        __syncthreads();
        if (tid == 0) out[p] = red[0] + red[1] + red[2] + red[3] + b2v;
        __syncthreads();
    }
}

// ---------------------------------------------------------------------------
extern "C" void kernel_launch(void* const* d_in, const int* in_sizes, int n_in,
                              void* d_out, int out_size)
{
    const float* x     = (const float*)d_in[0];
    const float* emask = (const float*)d_in[1];
    const int*   etype = (const int*)d_in[2];
    const int*   src   = (const int*)d_in[3];
    const int*   dst   = (const int*)d_in[4];
    const int*   users = (const int*)d_in[5];
    const int*   items = (const int*)d_in[6];
    const float* V1    = (const float*)d_in[7];
    const float* comp1 = (const float*)d_in[8];
    const float* loop1 = (const float*)d_in[9];
    const float* b1    = (const float*)d_in[10];
    const float* V2    = (const float*)d_in[11];
    const float* comp2 = (const float*)d_in[12];
    const float* loop2 = (const float*)d_in[13];
    const float* b2    = (const float*)d_in[14];
    const float* V3    = (const float*)d_in[15];
    const float* comp3 = (const float*)d_in[16];
    const float* loop3 = (const float*)d_in[17];
    const float* b3    = (const float*)d_in[18];
    const float* w1    = (const float*)d_in[19];
    const float* bw1   = (const float*)d_in[20];
    const float* w2    = (const float*)d_in[21];
    const float* bw2   = (const float*)d_in[22];
    float* out = (float*)d_out;

    float *xb, *agg, *h1, *h2, *h3;
    int *deg, *bsum, *rowptr, *cursor;
    int4* meta;
    cudaGetSymbolAddress((void**)&xb,     g_xb);
    cudaGetSymbolAddress((void**)&agg,    g_agg);
    cudaGetSymbolAddress((void**)&h1,     g_h1);
    cudaGetSymbolAddress((void**)&h2,     g_h2);
    cudaGetSymbolAddress((void**)&h3,     g_h3);
    cudaGetSymbolAddress((void**)&deg,    g_deg);
    cudaGetSymbolAddress((void**)&bsum,   g_bsum);
    cudaGetSymbolAddress((void**)&rowptr, g_rowptr);
    cudaGetSymbolAddress((void**)&cursor, g_cursor);
    cudaGetSymbolAddress((void**)&meta,   g_meta);

    const int smem_t1 = (INF * 96 + 32 * INF) * 4;
    const int smem_t2 = (HID * 96 + 32 * HID) * 4;
    const int smem_hd = (24576 + 192) * 4;
    cudaFuncSetAttribute(transform_kernel<INF>, cudaFuncAttributeMaxDynamicSharedMemorySize, smem_t1);
    cudaFuncSetAttribute(transform_kernel<HID>, cudaFuncAttributeMaxDynamicSharedMemorySize, smem_t2);
    cudaFuncSetAttribute(head_kernel, cudaFuncAttributeMaxDynamicSharedMemorySize, smem_hd);

    const int tgrid = (NN + 31) / 32;
    const int agrid = (NN * 32 + 255) / 256;   // warp-per-node, 8 warps/block

    // ---- CSR build (reused by all 3 layers) ----
    k_zero<<<(NN + 255) / 256, 256>>>(deg, NN);
    k_hist<<<(NE + 255) / 256, 256>>>(dst, deg, NE);
    k_blocksum<<<NB, SCAN_BS>>>(deg, bsum, NN);
    k_scantop<<<1, 128>>>(bsum, NB, rowptr + NN);
    k_scanapply<<<NB, SCAN_BS>>>(deg, bsum, rowptr, cursor, NN);
    k_scatter<<<(NE + 255) / 256, 256>>>(src, dst, etype, emask, cursor, meta, NE);

    // ---- Layer 1 ----
    transform_kernel<INF><<<tgrid, 96, smem_t1>>>(x, V1, loop1, b1, xb, agg, NN);
    k_aggregate<<<agrid, 256>>>(xb, agg, rowptr, meta, comp1, h1, NN);
    // ---- Layer 2 ----
    transform_kernel<HID><<<tgrid, 96, smem_t2>>>(h1, V2, loop2, b2, xb, agg, NN);
    k_aggregate<<<agrid, 256>>>(xb, agg, rowptr, meta, comp2, h2, NN);
    // ---- Layer 3 ----
    transform_kernel<HID><<<tgrid, 96, smem_t2>>>(h2, V3, loop3, b3, xb, agg, NN);
    k_aggregate<<<agrid, 256>>>(xb, agg, rowptr, meta, comp3, h3, NN);
    // ---- Head ----
    head_kernel<<<(NPAIRS + PPB - 1) / PPB, 128, smem_hd>>>(
        h1, h2, h3, users, items, w1, bw1, w2, bw2, out, NPAIRS);
}

// round 3
// speedup vs baseline: 1.8727x; 1.2518x over previous
#include <cuda_runtime.h>
#include <cuda_bf16.h>
#include <math.h>

#define NN 100000
#define NE 1600000
#define INF 128
#define HID 32
#define NPAIRS 4096
#define SCAN_BS 1024
#define NB ((NN + SCAN_BS - 1) / SCAN_BS)   // 98

// scratch (device globals)
__device__ float g_xb[NN * 64];        // basis outputs interleaved [n][o*2+b]
__device__ float g_agg[NN * 32];       // agg init (loop term + bias)
__device__ float g_h1[NN * 32];
__device__ float g_h2[NN * 32];
__device__ float g_h3[NN * 32];
__device__ int   g_deg[NN];
__device__ int   g_bsum[NB + 1];
__device__ int   g_rowptr[NN + 1];
__device__ int   g_cursor[NN];
__device__ int4  g_meta[NE];           // {src, etype, mask_bits, 0} grouped by dst

// ---------------------------------------------------------------------------
// Split-TF32 tensor-core transform.
// out96[n][j] = sum_d x[n][d]*Wall[d][j];  j<64 -> xb (interleaved), j>=64 -> agg+bias
// Block: 128 nodes x 96 outs, 8 warps (warp tile 32x48), K chunked by 32.
// ---------------------------------------------------------------------------
#define XS_STRIDE 36    // float2 units; bank-conflict-free for A frags
#define WS_STRIDE 100   // float2 units; bank-conflict-free for B frags
#define OS_STRIDE 104   // float  units; conflict-free C restage
#define XS_BYTES  (128 * XS_STRIDE * 8)           // 36864
#define WS_BYTES  (32 * WS_STRIDE * 8)            // 25600
#define TSMEM     (XS_BYTES + WS_BYTES)           // 62464 (outs 128*104*4=53248 fits)

__device__ __forceinline__ unsigned f2tf(float f) {
    unsigned r; asm("cvt.rna.tf32.f32 %0, %1;" : "=r"(r) : "f"(f)); return r;
}
__device__ __forceinline__ void mma8(float* c, const unsigned* a, const unsigned* b) {
    asm volatile("mma.sync.aligned.m16n8k8.row.col.f32.tf32.tf32.f32 "
                 "{%0,%1,%2,%3}, {%4,%5,%6,%7}, {%8,%9}, {%0,%1,%2,%3};"
                 : "+f"(c[0]), "+f"(c[1]), "+f"(c[2]), "+f"(c[3])
                 : "r"(a[0]), "r"(a[1]), "r"(a[2]), "r"(a[3]), "r"(b[0]), "r"(b[1]));
}

template <int DIN>
__global__ __launch_bounds__(256, 2)
void transform_mma(const float* __restrict__ xin,
                   const float* __restrict__ V,       // [2][DIN][32]
                   const float* __restrict__ loopw,   // [DIN][32]
                   const float* __restrict__ bias,    // [32]
                   float* __restrict__ xb,
                   float* __restrict__ agg,
                   int nnodes)
{
    extern __shared__ char smraw[];
    float2* xs = (float2*)smraw;                 // [128][XS_STRIDE] {hi,lo}
    float2* ws = (float2*)(smraw + XS_BYTES);    // [32][WS_STRIDE]  {hi,lo}
    float*  outs = (float*)smraw;                // reused after compute

    const int tid = threadIdx.x;
    const int lane = tid & 31, wid = tid >> 5;
    const int warpM = wid & 3, warpN = wid >> 2;     // 4m x 2n
    const int gid = lane >> 2, tig = lane & 3;
    const int base = blockIdx.x * 128;

    float c[2][6][4];
#pragma unroll
    for (int mt = 0; mt < 2; mt++)
#pragma unroll
        for (int nt = 0; nt < 6; nt++)
#pragma unroll
            for (int q = 0; q < 4; q++) c[mt][nt][q] = 0.f;

    const int NCHUNK = DIN / 32;
#pragma unroll 1
    for (int ch = 0; ch < NCHUNK; ch++) {
        const int kbase = ch * 32;
        if (ch) __syncthreads();
        // stage x chunk (128 nodes x 32 k), split hi/lo
        for (int idx = tid; idx < 128 * 32; idx += 256) {
            int row = idx >> 5, col = idx & 31;
            int node = base + row;
            float v = (node < nnodes) ? xin[(long)node * DIN + kbase + col] : 0.f;
            unsigned hb = f2tf(v);
            float hf = __uint_as_float(hb);
            unsigned lb = f2tf(v - hf);
            xs[row * XS_STRIDE + col] = make_float2(hf, __uint_as_float(lb));
        }
        // stage W chunk (32 k x 96 j)
        for (int idx = tid; idx < 32 * 96; idx += 256) {
            int k = idx / 96, j = idx - k * 96;
            int d = kbase + k;
            float w = (j < 64) ? V[(j >> 5) * DIN * 32 + d * 32 + (j & 31)]
                               : loopw[d * 32 + (j - 64)];
            unsigned hb = f2tf(w);
            float hf = __uint_as_float(hb);
            unsigned lb = f2tf(w - hf);
            ws[k * WS_STRIDE + j] = make_float2(hf, __uint_as_float(lb));
        }
        __syncthreads();

#pragma unroll
        for (int ks = 0; ks < 32; ks += 8) {
            unsigned ahi[2][4], alo[2][4];
#pragma unroll
            for (int mt = 0; mt < 2; mt++) {
                int r0 = warpM * 32 + mt * 16 + gid;
                float2 a0 = xs[(r0    ) * XS_STRIDE + ks + tig];
                float2 a1 = xs[(r0 + 8) * XS_STRIDE + ks + tig];
                float2 a2 = xs[(r0    ) * XS_STRIDE + ks + tig + 4];
                float2 a3 = xs[(r0 + 8) * XS_STRIDE + ks + tig + 4];
                ahi[mt][0] = __float_as_uint(a0.x); alo[mt][0] = __float_as_uint(a0.y);
                ahi[mt][1] = __float_as_uint(a1.x); alo[mt][1] = __float_as_uint(a1.y);
                ahi[mt][2] = __float_as_uint(a2.x); alo[mt][2] = __float_as_uint(a2.y);
                ahi[mt][3] = __float_as_uint(a3.x); alo[mt][3] = __float_as_uint(a3.y);
            }
            unsigned bhi[6][2], blo[6][2];
#pragma unroll
            for (int nt = 0; nt < 6; nt++) {
                int n = warpN * 48 + nt * 8 + gid;
                float2 b0 = ws[(ks + tig    ) * WS_STRIDE + n];
                float2 b1 = ws[(ks + tig + 4) * WS_STRIDE + n];
                bhi[nt][0] = __float_as_uint(b0.x); blo[nt][0] = __float_as_uint(b0.y);
                bhi[nt][1] = __float_as_uint(b1.x); blo[nt][1] = __float_as_uint(b1.y);
            }
#pragma unroll
            for (int mt = 0; mt < 2; mt++)
#pragma unroll
                for (int nt = 0; nt < 6; nt++) {
                    mma8(c[mt][nt], ahi[mt], bhi[nt]);
                    mma8(c[mt][nt], ahi[mt], blo[nt]);
                    mma8(c[mt][nt], alo[mt], bhi[nt]);
                }
        }
    }
    __syncthreads();   // smem dead, reuse as outs

    // restage C to smem
#pragma unroll
    for (int mt = 0; mt < 2; mt++)
#pragma unroll
        for (int nt = 0; nt < 6; nt++) {
            int r0 = warpM * 32 + mt * 16 + gid;
            int c0 = warpN * 48 + nt * 8 + tig * 2;
            outs[(r0    ) * OS_STRIDE + c0    ] = c[mt][nt][0];
            outs[(r0    ) * OS_STRIDE + c0 + 1] = c[mt][nt][1];
            outs[(r0 + 8) * OS_STRIDE + c0    ] = c[mt][nt][2];
            outs[(r0 + 8) * OS_STRIDE + c0 + 1] = c[mt][nt][3];
        }
    __syncthreads();

    for (int idx = tid; idx < 128 * 96; idx += 256) {
        int row = idx / 96, j = idx - row * 96;
        int node = base + row;
        if (node >= nnodes) continue;
        float v = outs[row * OS_STRIDE + j];
        if (j < 64) xb[(long)node * 64 + (j & 31) * 2 + (j >> 5)] = v;
        else        agg[(long)node * 32 + (j - 64)] = v + bias[j - 64];
    }
}

// ------------------------ CSR build ---------------------------------------
__global__ void k_zero(int* p, int n)
{
    int i = blockIdx.x * blockDim.x + threadIdx.x;
    if (i < n) p[i] = 0;
}
__global__ void k_hist(const int* __restrict__ dst, int* __restrict__ deg, int ne)
{
    int i = blockIdx.x * blockDim.x + threadIdx.x;
    if (i < ne) atomicAdd(&deg[dst[i]], 1);
}
__global__ void k_blocksum(const int* __restrict__ deg, int* __restrict__ bsum, int n)
{
    __shared__ int wsum[32];
    int i = blockIdx.x * SCAN_BS + threadIdx.x;
    int v = (i < n) ? deg[i] : 0;
#pragma unroll
    for (int o = 16; o; o >>= 1) v += __shfl_down_sync(0xFFFFFFFFu, v, o);
    int lane = threadIdx.x & 31, wid = threadIdx.x >> 5;
    if (lane == 0) wsum[wid] = v;
    __syncthreads();
    if (wid == 0) {
        int x = wsum[lane];
#pragma unroll
        for (int o = 16; o; o >>= 1) x += __shfl_down_sync(0xFFFFFFFFu, x, o);
        if (lane == 0) bsum[blockIdx.x] = x;
    }
}
__global__ void k_scantop(int* __restrict__ bsum, int nb, int* __restrict__ rowptr_end)
{
    __shared__ int s[128];
    int t = threadIdx.x;
    int v = (t < nb) ? bsum[t] : 0;
    s[t] = v;
    __syncthreads();
#pragma unroll
    for (int o = 1; o < 128; o <<= 1) {
        int y = (t >= o) ? s[t - o] : 0;
        __syncthreads();
        s[t] += y;
        __syncthreads();
    }
    if (t < nb) bsum[t] = s[t] - v;
    if (t == 127) *rowptr_end = s[127];
}
__global__ void k_scanapply(const int* __restrict__ deg, const int* __restrict__ bsum,
                            int* __restrict__ rowptr, int* __restrict__ cursor, int n)
{
    __shared__ int wsum[32];
    int i = blockIdx.x * SCAN_BS + threadIdx.x;
    int v = (i < n) ? deg[i] : 0;
    int lane = threadIdx.x & 31, wid = threadIdx.x >> 5;
    unsigned fm = 0xFFFFFFFFu;
    int x = v;
#pragma unroll
    for (int o = 1; o < 32; o <<= 1) {
        int y = __shfl_up_sync(fm, x, o);
        if (lane >= o) x += y;
    }
    if (lane == 31) wsum[wid] = x;
    __syncthreads();
    if (wid == 0) {
        int w = wsum[lane];
        int wx = w;
#pragma unroll
        for (int o = 1; o < 32; o <<= 1) {
            int y = __shfl_up_sync(fm, wx, o);
            if (lane >= o) wx += y;
        }
        wsum[lane] = wx - w;
    }
    __syncthreads();
    int excl = (x - v) + wsum[wid] + bsum[blockIdx.x];
    if (i < n) { rowptr[i] = excl; cursor[i] = excl; }
}
__global__ void k_scatter(const int* __restrict__ src, const int* __restrict__ dst,
                          const int* __restrict__ etype, const float* __restrict__ mask,
                          int* __restrict__ cursor, int4* __restrict__ meta, int ne)
{
    int e = blockIdx.x * blockDim.x + threadIdx.x;
    if (e >= ne) return;
    int d = dst[e];
    int pos = atomicAdd(&cursor[d], 1);
    meta[pos] = make_int4(src[e], etype[e], __float_as_int(mask[e]), 0);
}

// ---------------------------------------------------------------------------
// Aggregate: warp per node, 4-edge batched loads for MLP.
// ---------------------------------------------------------------------------
__global__ void k_aggregate(const float* __restrict__ xb,
                            const float* __restrict__ agginit,
                            const int* __restrict__ rowptr,
                            const int4* __restrict__ meta,
                            const float* __restrict__ comp,
                            float* __restrict__ h, int nn)
{
    __shared__ float cl[16];
    if (threadIdx.x < 10) cl[threadIdx.x] = comp[threadIdx.x];
    __syncthreads();
    const int lane = threadIdx.x & 31;
    const int w = (blockIdx.x * blockDim.x + threadIdx.x) >> 5;
    if (w >= nn) return;
    float acc = agginit[(long)w * 32 + lane];
    int i = rowptr[w];
    const int end = rowptr[w + 1];
    for (; i + 4 <= end; i += 4) {
        int4 m0 = __ldg(&meta[i]);
        int4 m1 = __ldg(&meta[i + 1]);
        int4 m2 = __ldg(&meta[i + 2]);
        int4 m3 = __ldg(&meta[i + 3]);
        float2 v0 = *(const float2*)(xb + (long)m0.x * 64 + lane * 2);
        float2 v1 = *(const float2*)(xb + (long)m1.x * 64 + lane * 2);
        float2 v2 = *(const float2*)(xb + (long)m2.x * 64 + lane * 2);
        float2 v3 = *(const float2*)(xb + (long)m3.x * 64 + lane * 2);
        acc = fmaf(__int_as_float(m0.z), fmaf(cl[m0.y * 2], v0.x, cl[m0.y * 2 + 1] * v0.y), acc);
        acc = fmaf(__int_as_float(m1.z), fmaf(cl[m1.y * 2], v1.x, cl[m1.y * 2 + 1] * v1.y), acc);
        acc = fmaf(__int_as_float(m2.z), fmaf(cl[m2.y * 2], v2.x, cl[m2.y * 2 + 1] * v2.y), acc);
        acc = fmaf(__int_as_float(m3.z), fmaf(cl[m3.y * 2], v3.x, cl[m3.y * 2 + 1] * v3.y), acc);
    }
    for (; i < end; i++) {
        int4 md = __ldg(&meta[i]);
        float2 v = *(const float2*)(xb + (long)md.x * 64 + lane * 2);
        acc = fmaf(__int_as_float(md.z), fmaf(cl[md.y * 2], v.x, cl[md.y * 2 + 1] * v.y), acc);
    }
    h[(long)w * 32 + lane] = tanhf(acc);
}

// ---------------------------------------------------------------------------
#define PPB 32
__global__ void head_kernel(const float* __restrict__ h1,
                            const float* __restrict__ h2,
                            const float* __restrict__ h3,
                            const int* __restrict__ users,
                            const int* __restrict__ items,
                            const float* __restrict__ w1,
                            const float* __restrict__ bw1,
                            const float* __restrict__ w2,
                            const float* __restrict__ bw2,
                            float* __restrict__ out,
                            int npairs)
{
    extern __shared__ float sm[];
    float* w1s = sm;
    float* feats = sm + 24576;
    const int tid = threadIdx.x;

    for (int idx = tid; idx < 24576; idx += 128) w1s[idx] = w1[idx];
    const float bb = bw1[tid];
    const float wv2 = w2[tid];
    const float b2v = bw2[0];
    __shared__ float red[4];
    __syncthreads();

    const int pend = min((blockIdx.x + 1) * PPB, npairs);
    for (int p = blockIdx.x * PPB; p < pend; p++) {
        if (tid < 96) {
            int u = __ldg(&users[p]);
            int it = __ldg(&items[p]);
            int o = tid & 31;
            const float* hu = (tid < 32) ? h1 : (tid < 64) ? h2 : h3;
            feats[tid] = hu[(long)u * 32 + o];
            feats[96 + tid] = hu[(long)it * 32 + o];
        }
        __syncthreads();
        float acc = bb;
#pragma unroll 16
        for (int k = 0; k < 192; k++)
            acc = fmaf(feats[k], w1s[k * 128 + tid], acc);
        float hv = fmaxf(acc, 0.f) * wv2;
#pragma unroll
        for (int off = 16; off; off >>= 1) hv += __shfl_down_sync(0xFFFFFFFFu, hv, off);
        if ((tid & 31) == 0) red[tid >> 5] = hv;
        __syncthreads();
        if (tid == 0) out[p] = red[0] + red[1] + red[2] + red[3] + b2v;
        __syncthreads();
    }
}

// ---------------------------------------------------------------------------
extern "C" void kernel_launch(void* const* d_in, const int* in_sizes, int n_in,
                              void* d_out, int out_size)
{
    const float* x     = (const float*)d_in[0];
    const float* emask = (const float*)d_in[1];
    const int*   etype = (const int*)d_in[2];
    const int*   src   = (const int*)d_in[3];
    const int*   dst   = (const int*)d_in[4];
    const int*   users = (const int*)d_in[5];
    const int*   items = (const int*)d_in[6];
    const float* V1    = (const float*)d_in[7];
    const float* comp1 = (const float*)d_in[8];
    const float* loop1 = (const float*)d_in[9];
    const float* b1    = (const float*)d_in[10];
    const float* V2    = (const float*)d_in[11];
    const float* comp2 = (const float*)d_in[12];
    const float* loop2 = (const float*)d_in[13];
    const float* b2    = (const float*)d_in[14];
    const float* V3    = (const float*)d_in[15];
    const float* comp3 = (const float*)d_in[16];
    const float* loop3 = (const float*)d_in[17];
    const float* b3    = (const float*)d_in[18];
    const float* w1    = (const float*)d_in[19];
    const float* bw1   = (const float*)d_in[20];
    const float* w2    = (const float*)d_in[21];
    const float* bw2   = (const float*)d_in[22];
    float* out = (float*)d_out;

    float *xb, *agg, *h1, *h2, *h3;
    int *deg, *bsum, *rowptr, *cursor;
    int4* meta;
    cudaGetSymbolAddress((void**)&xb,     g_xb);
    cudaGetSymbolAddress((void**)&agg,    g_agg);
    cudaGetSymbolAddress((void**)&h1,     g_h1);
    cudaGetSymbolAddress((void**)&h2,     g_h2);
    cudaGetSymbolAddress((void**)&h3,     g_h3);
    cudaGetSymbolAddress((void**)&deg,    g_deg);
    cudaGetSymbolAddress((void**)&bsum,   g_bsum);
    cudaGetSymbolAddress((void**)&rowptr, g_rowptr);
    cudaGetSymbolAddress((void**)&cursor, g_cursor);
    cudaGetSymbolAddress((void**)&meta,   g_meta);

    const int smem_hd = (24576 + 192) * 4;
    cudaFuncSetAttribute(transform_mma<INF>, cudaFuncAttributeMaxDynamicSharedMemorySize, TSMEM);
    cudaFuncSetAttribute(transform_mma<HID>, cudaFuncAttributeMaxDynamicSharedMemorySize, TSMEM);
    cudaFuncSetAttribute(head_kernel, cudaFuncAttributeMaxDynamicSharedMemorySize, smem_hd);

    const int tgrid = (NN + 127) / 128;        // 782
    const int agrid = (NN * 32 + 255) / 256;   // 12500

    // CSR build (reused by all 3 layers)
    k_zero<<<(NN + 255) / 256, 256>>>(deg, NN);
    k_hist<<<(NE + 255) / 256, 256>>>(dst, deg, NE);
    k_blocksum<<<NB, SCAN_BS>>>(deg, bsum, NN);
    k_scantop<<<1, 128>>>(bsum, NB, rowptr + NN);
    k_scanapply<<<NB, SCAN_BS>>>(deg, bsum, rowptr, cursor, NN);
    k_scatter<<<(NE + 255) / 256, 256>>>(src, dst, etype, emask, cursor, meta, NE);

    // Layer 1
    transform_mma<INF><<<tgrid, 256, TSMEM>>>(x, V1, loop1, b1, xb, agg, NN);
    k_aggregate<<<agrid, 256>>>(xb, agg, rowptr, meta, comp1, h1, NN);
    // Layer 2
    transform_mma<HID><<<tgrid, 256, TSMEM>>>(h1, V2, loop2, b2, xb, agg, NN);
    k_aggregate<<<agrid, 256>>>(xb, agg, rowptr, meta, comp2, h2, NN);
    // Layer 3
    transform_mma<HID><<<tgrid, 256, TSMEM>>>(h2, V3, loop3, b3, xb, agg, NN);
    k_aggregate<<<agrid, 256>>>(xb, agg, rowptr, meta, comp3, h3, NN);
    // Head
    head_kernel<<<(NPAIRS + PPB - 1) / PPB, 128, smem_hd>>>(
        h1, h2, h3, users, items, w1, bw1, w2, bw2, out, NPAIRS);
}